// round 3
// baseline (speedup 1.0000x reference)
#include <cuda_runtime.h>

// ----------------------------------------------------------------------------
// GAT encoder: 3 layers, N=50000 nodes, E=1.6M edges (+N self loops).
//   1. Detect edge_index dtype (int32 vs int64) on device — JAX silently
//      downcasts jnp.int64 -> int32 when x64 mode is off.
//   2. Build CSR (by dst): histogram + single-block scan + fill.
//   3. Per layer: GEMM -> attention scalars -> warp-per-node softmax-agg.
// All scratch in __device__ globals. Graph-capturable: kernel launches only.
// All indexed writes are bounds-clamped so a bad index can never corrupt the
// context (fails soft with rel_err instead of killing the container).
// ----------------------------------------------------------------------------

#define NN    50000
#define EMAX  1600000
#define ETOT  (EMAX + NN)
#define HST   132          // padded row stride for h / x buffers
#define NEG   0.2f

__device__ int   g_is64;
__device__ int   g_cnt[NN];
__device__ int   g_off[NN + 1];
__device__ int   g_cur[NN];
__device__ int   g_csr[ETOT];
__device__ float g_h[(size_t)NN * HST];
__device__ float g_x[(size_t)NN * HST];
__device__ float g_als[NN * 4];   // stride 4 so 3 heads = one LDG.128
__device__ float g_ald[NN * 4];

__device__ __forceinline__ float lrelu(float v) { return v >= 0.f ? v : NEG * v; }

__device__ __forceinline__ int edge_at(const void* ei, size_t idx, int is64) {
    if (is64) return (int)((const long long*)ei)[idx];
    return ((const int*)ei)[idx];
}

// ---------------- dtype detection ----------------
// int64 little-endian values < 2^32 have zero high words at odd 32-bit slots.
// int32 data has random node indices there; 128 all-zero is impossible.
__global__ void k_detect(const unsigned int* __restrict__ w) {
    if (threadIdx.x == 0 && blockIdx.x == 0) {
        int all0 = 1;
        for (int i = 1; i < 256; i += 2)
            if (w[i] != 0u) { all0 = 0; break; }
        g_is64 = all0;
    }
}

// ---------------- CSR build ----------------

__global__ void k_initcnt(int n) {
    int i = blockIdx.x * blockDim.x + threadIdx.x;
    if (i < n) g_cnt[i] = 1;   // self loop
}

__global__ void k_count(const void* __restrict__ ei, int E, int n) {
    int i = blockIdx.x * blockDim.x + threadIdx.x;
    if (i >= E) return;
    int is64 = g_is64;
    int d = edge_at(ei, (size_t)E + i, is64);
    if ((unsigned)d < (unsigned)n) atomicAdd(&g_cnt[d], 1);
}

// single-block exclusive scan of g_cnt[0..n) -> g_off[0..n], also g_cur copy
__global__ void k_scan(int n) {
    __shared__ int sd[1024];
    __shared__ int carry;
    int tid = threadIdx.x;
    if (tid == 0) carry = 0;
    __syncthreads();
    for (int base = 0; base < n; base += 1024) {
        int v = (base + tid < n) ? g_cnt[base + tid] : 0;
        sd[tid] = v;
        __syncthreads();
        for (int off = 1; off < 1024; off <<= 1) {
            int t = (tid >= off) ? sd[tid - off] : 0;
            __syncthreads();
            sd[tid] += t;
            __syncthreads();
        }
        int c = carry;
        if (base + tid < n) {
            int ex = c + sd[tid] - v;
            g_off[base + tid] = ex;
            g_cur[base + tid] = ex;
        }
        __syncthreads();
        if (tid == 0) carry = c + sd[1023];
        __syncthreads();
    }
    if (tid == 0) g_off[n] = carry;
}

__global__ void k_fill(const void* __restrict__ ei, int E, int n) {
    int i = blockIdx.x * blockDim.x + threadIdx.x;
    if (i >= E + n) return;
    int s, d;
    if (i < E) {
        int is64 = g_is64;
        s = edge_at(ei, (size_t)i, is64);
        d = edge_at(ei, (size_t)E + i, is64);
    } else {
        s = i - E; d = s;
    }
    if ((unsigned)s >= (unsigned)n || (unsigned)d >= (unsigned)n) return;
    int p = atomicAdd(&g_cur[d], 1);
    if ((unsigned)p < (unsigned)ETOT) g_csr[p] = s;
}

// ---------------- GEMM: h = x @ W (h stride = HST) ----------------
// Block = 256 threads = 8 warps, each warp computes 8 nodes x FOUT (<=129).
// Lane handles features {lane, lane+32, lane+64, lane+96, [lane+128]}.

__global__ __launch_bounds__(256) void k_gemm(
    const float* __restrict__ xext, int use_ext, int xstride, int K,
    const float* __restrict__ W, int FOUT, int n)
{
    __shared__ float sx[64 * 129];
    const float* x = use_ext ? xext : g_x;
    int tid = threadIdx.x, warp = tid >> 5, lane = tid & 31;
    int nb = blockIdx.x * 64;

    int tot = 64 * K;
    for (int idx = tid; idx < tot; idx += 256) {
        int nl = idx / K, k = idx - nl * K;
        int gn = nb + nl;
        sx[idx] = (gn < n) ? x[(size_t)gn * xstride + k] : 0.f;
    }
    __syncthreads();

    float acc[8][5];
#pragma unroll
    for (int a = 0; a < 8; a++)
#pragma unroll
        for (int j = 0; j < 5; j++) acc[a][j] = 0.f;

    bool v4 = (lane + 128) < FOUT;        // FOUT is 128 or 129
    const float* sxw = sx + warp * 8 * K;

    for (int k = 0; k < K; k++) {
        const float* Wr = W + (size_t)k * FOUT + lane;
        float wv[5];
#pragma unroll
        for (int j = 0; j < 4; j++) wv[j] = __ldg(&Wr[32 * j]);
        wv[4] = v4 ? __ldg(&Wr[128]) : 0.f;
#pragma unroll
        for (int a = 0; a < 8; a++) {
            float xv = sxw[a * K + k];
#pragma unroll
            for (int j = 0; j < 5; j++) acc[a][j] = fmaf(xv, wv[j], acc[a][j]);
        }
    }

#pragma unroll
    for (int a = 0; a < 8; a++) {
        int gn = nb + warp * 8 + a;
        if (gn < n) {
            float* hr = g_h + (size_t)gn * HST;
#pragma unroll
            for (int j = 0; j < 4; j++) hr[lane + 32 * j] = acc[a][j];
            if (v4) hr[lane + 128] = acc[a][4];
        }
    }
}

// ---------------- per-(node, head) attention scalars ----------------

__global__ void k_al(const float* __restrict__ asr, const float* __restrict__ adt,
                     int H, int F, int n)
{
    int i = blockIdx.x * blockDim.x + threadIdx.x;
    if (i >= n * H) return;
    int nd = i / H, hd = i - nd * H;
    const float* hr = g_h + (size_t)nd * HST + hd * F;
    const float* as = asr + hd * F;
    const float* ad = adt + hd * F;
    float s = 0.f, d = 0.f;
    for (int f = 0; f < F; f++) {
        float v = hr[f];
        s = fmaf(v, as[f], s);
        d = fmaf(v, ad[f], d);
    }
    g_als[nd * 4 + hd] = s;
    g_ald[nd * 4 + hd] = d;
}

// ---------------- warp-per-node softmax aggregation ----------------

template <int H, int F, bool LR, bool OUT_EXT>
__global__ __launch_bounds__(256) void k_agg(
    const float* __restrict__ bias, float* __restrict__ outext,
    int ostride, int n)
{
    constexpr int FOUT = H * F;
    constexpr int NJ = (FOUT + 31) / 32;

    int warp = (blockIdx.x * blockDim.x + threadIdx.x) >> 5;
    int lane = threadIdx.x & 31;
    if (warp >= n) return;
    int d = warp;

    float* out = OUT_EXT ? outext : g_x;

    int r0 = g_off[d], r1 = g_off[d + 1];
    if (r1 <= r0) r1 = r0;   // defensive

    float4 ad4 = *reinterpret_cast<const float4*>(&g_ald[d * 4]);
    float aldv[3] = {ad4.x, ad4.y, ad4.z};

    // pass 1: per-head max (lane-parallel over edges)
    float m[H];
#pragma unroll
    for (int t = 0; t < H; t++) m[t] = -3.4e38f;
    for (int e = r0 + lane; e < r1; e += 32) {
        int s = __ldg(&g_csr[e]);
        float4 a4 = *reinterpret_cast<const float4*>(&g_als[s * 4]);
        float av[3] = {a4.x, a4.y, a4.z};
#pragma unroll
        for (int t = 0; t < H; t++) {
            float v = lrelu(av[t] + aldv[t]);
            m[t] = fmaxf(m[t], v);
        }
    }
#pragma unroll
    for (int o = 16; o > 0; o >>= 1)
#pragma unroll
        for (int t = 0; t < H; t++) m[t] = fmaxf(m[t], __shfl_xor_sync(0xffffffffu, m[t], o));

    // feature assignment (fixed per lane)
    int fidx[NJ];
    int hidx[NJ];
    bool fval[NJ];
#pragma unroll
    for (int j = 0; j < NJ; j++) {
        fidx[j] = lane + 32 * j;
        fval[j] = fidx[j] < FOUT;
        hidx[j] = fval[j] ? (fidx[j] / F) : 0;
    }

    // pass 2: weighted accumulation + denominator (edges sequential, prefetched)
    float acc[NJ];
#pragma unroll
    for (int j = 0; j < NJ; j++) acc[j] = 0.f;
    float den[H];
#pragma unroll
    for (int t = 0; t < H; t++) den[t] = 0.f;

    if (r1 > r0) {
        int   s_cur = __ldg(&g_csr[r0]);
        float4 a_cur = *reinterpret_cast<const float4*>(&g_als[s_cur * 4]);

        for (int e = r0; e < r1; e++) {
            int e2 = (e + 1 < r1) ? (e + 1) : e;       // clamped prefetch index
            int s_nxt = __ldg(&g_csr[e2]);
            float4 a_nxt = *reinterpret_cast<const float4*>(&g_als[s_nxt * 4]);

            float av[3] = {a_cur.x, a_cur.y, a_cur.z};
            float w[H];
#pragma unroll
            for (int t = 0; t < H; t++) {
                float v = lrelu(av[t] + aldv[t]);
                w[t] = __expf(v - m[t]);
                den[t] += w[t];
            }
            const float* hr = g_h + (size_t)s_cur * HST;
#pragma unroll
            for (int j = 0; j < NJ; j++) {
                if (fval[j]) {
                    float wj;
                    if (H == 1) wj = w[0];
                    else        wj = (hidx[j] == 0) ? w[0] : ((hidx[j] == 1) ? w[1] : w[2]);
                    acc[j] = fmaf(wj, __ldg(&hr[fidx[j]]), acc[j]);
                }
            }
            s_cur = s_nxt; a_cur = a_nxt;
        }
    }

    float inv[H];
#pragma unroll
    for (int t = 0; t < H; t++) inv[t] = 1.f / (den[t] + 1e-16f);

    float* orow = out + (size_t)d * ostride;
#pragma unroll
    for (int j = 0; j < NJ; j++) {
        if (fval[j]) {
            float ij;
            if (H == 1) ij = inv[0];
            else        ij = (hidx[j] == 0) ? inv[0] : ((hidx[j] == 1) ? inv[1] : inv[2]);
            float v = fmaf(acc[j], ij, 0.f) + __ldg(&bias[fidx[j]]);
            if (LR) v = lrelu(v);
            orow[fidx[j]] = v;
        }
    }
}

// ---------------- launch ----------------

extern "C" void kernel_launch(void* const* d_in, const int* in_sizes, int n_in,
                              void* d_out, int out_size)
{
    const float* x   = (const float*)d_in[0];
    const void*  ei  = d_in[1];
    const float* W0  = (const float*)d_in[2];
    const float* as0 = (const float*)d_in[3];
    const float* ad0 = (const float*)d_in[4];
    const float* b0  = (const float*)d_in[5];
    const float* W1  = (const float*)d_in[6];
    const float* as1 = (const float*)d_in[7];
    const float* ad1 = (const float*)d_in[8];
    const float* b1  = (const float*)d_in[9];
    const float* W2  = (const float*)d_in[10];
    const float* as2 = (const float*)d_in[11];
    const float* ad2 = (const float*)d_in[12];
    const float* b2  = (const float*)d_in[13];

    int n = in_sizes[0] / 6;       // 50000
    int E = in_sizes[1] / 2;       // 1600000
    if (n > NN) n = NN;
    if (E > EMAX) E = EMAX;

    // dtype detection + CSR build
    k_detect<<<1, 32>>>((const unsigned int*)ei);
    k_initcnt<<<(n + 255) / 256, 256>>>(n);
    k_count<<<(E + 255) / 256, 256>>>(ei, E, n);
    k_scan<<<1, 1024>>>(n);
    k_fill<<<(E + n + 255) / 256, 256>>>(ei, E, n);

    int gemm_blocks = (n + 63) / 64;
    int agg_blocks  = (n + 7) / 8;

    // layer 0: in=6 -> 3x43 (concat 129), lrelu
    k_gemm<<<gemm_blocks, 256>>>(x, 1, 6, 6, W0, 129, n);
    k_al<<<(n * 3 + 255) / 256, 256>>>(as0, ad0, 3, 43, n);
    k_agg<3, 43, true, false><<<agg_blocks, 256>>>(b0, nullptr, HST, n);

    // layer 1: 129 -> 3x43 (concat 129), lrelu
    k_gemm<<<gemm_blocks, 256>>>(nullptr, 0, HST, 129, W1, 129, n);
    k_al<<<(n * 3 + 255) / 256, 256>>>(as1, ad1, 3, 43, n);
    k_agg<3, 43, true, false><<<agg_blocks, 256>>>(b1, nullptr, HST, n);

    // layer 2: 129 -> 1x128 (mean over 1 head), no final activation
    k_gemm<<<gemm_blocks, 256>>>(nullptr, 0, HST, 129, W2, 128, n);
    k_al<<<(n + 255) / 256, 256>>>(as2, ad2, 1, 128, n);
    k_agg<1, 128, false, true><<<agg_blocks, 256>>>(b2, (float*)d_out, 128, n);
}

// round 4
// speedup vs baseline: 1.1168x; 1.1168x over previous
#include <cuda_runtime.h>

// ----------------------------------------------------------------------------
// GAT encoder: 3 layers, N=50000 nodes, E=1.6M edges (+N self loops).
// R4 changes vs R3 (772us):
//   - multi-block warp-shuffle scan (was 85us single-block -> ~12us)
//   - k_al rewritten warp-per-node, coalesced lane-over-feature loads
//   - k_agg pass2 unrolled 2 edges/iter, branch-free, depth-2 prefetch
//   - detect merged into init kernel
// ----------------------------------------------------------------------------

#define NN    50000
#define EMAX  1600000
#define ETOT  (EMAX + NN)
#define HST   132          // padded row stride for h / x buffers
#define NEG   0.2f

__device__ int   g_is64;
__device__ int   g_cnt[NN];
__device__ int   g_off[NN + 1];
__device__ int   g_cur[NN];
__device__ int   g_part[64];
__device__ int   g_csr[ETOT];
__device__ float g_h[(size_t)NN * HST];
__device__ float g_x[(size_t)NN * HST];
__device__ float g_als[NN * 4];   // stride 4 so 3 heads = one LDG.128
__device__ float g_ald[NN * 4];

__device__ __forceinline__ float lrelu(float v) { return v >= 0.f ? v : NEG * v; }

__device__ __forceinline__ int edge_at(const void* ei, size_t idx, int is64) {
    if (is64) return (int)((const long long*)ei)[idx];
    return ((const int*)ei)[idx];
}

// ---------------- init counts + dtype detection ----------------
// int64 little-endian values < 2^32 have zero high words at odd 32-bit slots.
__global__ void k_init(const unsigned int* __restrict__ w, int n) {
    int i = blockIdx.x * blockDim.x + threadIdx.x;
    if (i < n) g_cnt[i] = 1;   // self loop
    if (i == 0) {
        int all0 = 1;
        for (int j = 1; j < 256; j += 2)
            if (w[j] != 0u) { all0 = 0; break; }
        g_is64 = all0;
    }
}

__global__ void k_count(const void* __restrict__ ei, int E, int n) {
    int i = blockIdx.x * blockDim.x + threadIdx.x;
    if (i >= E) return;
    int is64 = g_is64;
    int d = edge_at(ei, (size_t)E + i, is64);
    if ((unsigned)d < (unsigned)n) atomicAdd(&g_cnt[d], 1);
}

// ---------------- multi-block exclusive scan ----------------
// scan1: per-block exclusive scan of g_cnt -> g_off, block sums -> g_part
// scan2: exclusive scan of g_part (single block), grand total -> g_off[n]
// scan3: add block offset, copy to g_cur

__device__ __forceinline__ int blockScanExcl(int v, int tid, int* smem) {
    int lane = tid & 31, wid = tid >> 5;
    int x = v;
#pragma unroll
    for (int o = 1; o < 32; o <<= 1) {
        int t = __shfl_up_sync(0xffffffffu, x, o);
        if (lane >= o) x += t;
    }
    if (lane == 31) smem[wid] = x;
    __syncthreads();
    if (wid == 0) {
        int y = smem[lane];
#pragma unroll
        for (int o = 1; o < 32; o <<= 1) {
            int t = __shfl_up_sync(0xffffffffu, y, o);
            if (lane >= o) y += t;
        }
        smem[lane] = y;
    }
    __syncthreads();
    int base = (wid > 0) ? smem[wid - 1] : 0;
    return base + x - v;   // exclusive
}

__global__ __launch_bounds__(1024) void k_scan1(int n) {
    __shared__ int sw[32];
    int tid = threadIdx.x;
    int i = blockIdx.x * 1024 + tid;
    int v = (i < n) ? g_cnt[i] : 0;
    int ex = blockScanExcl(v, tid, sw);
    if (i < n) g_off[i] = ex;
    if (tid == 1023) g_part[blockIdx.x] = ex + v;   // block total
}

__global__ __launch_bounds__(1024) void k_scan2(int nblk) {
    __shared__ int sw[32];
    int tid = threadIdx.x;
    int v = (tid < nblk) ? g_part[tid] : 0;
    int ex = blockScanExcl(v, tid, sw);
    if (tid < nblk) g_part[tid] = ex;
    if (tid == nblk - 1) g_off[NN] = ex + v;        // grand total at [n]==NN? use dynamic below
}

__global__ __launch_bounds__(1024) void k_scan3(int n) {
    int i = blockIdx.x * 1024 + threadIdx.x;
    if (i < n) {
        int o = g_off[i] + g_part[blockIdx.x];
        g_off[i] = o;
        g_cur[i] = o;
    }
}

__global__ void k_total(int n) {   // place grand total at g_off[n] for any n
    if (threadIdx.x == 0) {
        // g_off[NN] was written by scan2; move if n != NN
        if (n != NN) g_off[n] = g_off[NN];
    }
}

__global__ void k_fill(const void* __restrict__ ei, int E, int n) {
    int i = blockIdx.x * blockDim.x + threadIdx.x;
    if (i >= E + n) return;
    int s, d;
    if (i < E) {
        int is64 = g_is64;
        s = edge_at(ei, (size_t)i, is64);
        d = edge_at(ei, (size_t)E + i, is64);
    } else {
        s = i - E; d = s;
    }
    if ((unsigned)s >= (unsigned)n || (unsigned)d >= (unsigned)n) return;
    int p = atomicAdd(&g_cur[d], 1);
    if ((unsigned)p < (unsigned)ETOT) g_csr[p] = s;
}

// ---------------- GEMM: h = x @ W (h stride = HST) ----------------

__global__ __launch_bounds__(256) void k_gemm(
    const float* __restrict__ xext, int use_ext, int xstride, int K,
    const float* __restrict__ W, int FOUT, int n)
{
    __shared__ float sx[64 * 129];
    const float* x = use_ext ? xext : g_x;
    int tid = threadIdx.x, warp = tid >> 5, lane = tid & 31;
    int nb = blockIdx.x * 64;

    int tot = 64 * K;
    for (int idx = tid; idx < tot; idx += 256) {
        int nl = idx / K, k = idx - nl * K;
        int gn = nb + nl;
        sx[idx] = (gn < n) ? x[(size_t)gn * xstride + k] : 0.f;
    }
    __syncthreads();

    float acc[8][5];
#pragma unroll
    for (int a = 0; a < 8; a++)
#pragma unroll
        for (int j = 0; j < 5; j++) acc[a][j] = 0.f;

    bool v4 = (lane + 128) < FOUT;        // FOUT is 128 or 129
    const float* sxw = sx + warp * 8 * K;

    for (int k = 0; k < K; k++) {
        const float* Wr = W + (size_t)k * FOUT + lane;
        float wv[5];
#pragma unroll
        for (int j = 0; j < 4; j++) wv[j] = __ldg(&Wr[32 * j]);
        wv[4] = v4 ? __ldg(&Wr[128]) : 0.f;
#pragma unroll
        for (int a = 0; a < 8; a++) {
            float xv = sxw[a * K + k];
#pragma unroll
            for (int j = 0; j < 5; j++) acc[a][j] = fmaf(xv, wv[j], acc[a][j]);
        }
    }

#pragma unroll
    for (int a = 0; a < 8; a++) {
        int gn = nb + warp * 8 + a;
        if (gn < n) {
            float* hr = g_h + (size_t)gn * HST;
#pragma unroll
            for (int j = 0; j < 4; j++) hr[lane + 32 * j] = acc[a][j];
            if (v4) hr[lane + 128] = acc[a][4];
        }
    }
}

// ---------------- attention scalars: warp per node, coalesced ----------------

template <int H, int F>
__global__ __launch_bounds__(256) void k_al(
    const float* __restrict__ asr, const float* __restrict__ adt, int n)
{
    constexpr int FOUT = H * F;
    constexpr int NJ = (FOUT + 31) / 32;

    int warp = (blockIdx.x * blockDim.x + threadIdx.x) >> 5;
    int lane = threadIdx.x & 31;
    if (warp >= n) return;

    const float* hr = g_h + (size_t)warp * HST;

    float ps[H], pd[H];
#pragma unroll
    for (int t = 0; t < H; t++) { ps[t] = 0.f; pd[t] = 0.f; }

#pragma unroll
    for (int j = 0; j < NJ; j++) {
        int f = lane + 32 * j;
        if (f < FOUT) {
            float v = hr[f];
            float cs = v * __ldg(&asr[f]);
            float cd = v * __ldg(&adt[f]);
#pragma unroll
            for (int t = 0; t < H; t++) {
                bool in_t = (f >= t * F) && (f < (t + 1) * F);
                ps[t] += in_t ? cs : 0.f;
                pd[t] += in_t ? cd : 0.f;
            }
        }
    }
#pragma unroll
    for (int o = 16; o > 0; o >>= 1)
#pragma unroll
        for (int t = 0; t < H; t++) {
            ps[t] += __shfl_xor_sync(0xffffffffu, ps[t], o);
            pd[t] += __shfl_xor_sync(0xffffffffu, pd[t], o);
        }
    if (lane < H) {
        g_als[warp * 4 + lane] = (lane == 0) ? ps[0] : ((lane == 1 && H > 1) ? ps[1] : ps[H - 1]);
        g_ald[warp * 4 + lane] = (lane == 0) ? pd[0] : ((lane == 1 && H > 1) ? pd[1] : pd[H - 1]);
    }
}

// ---------------- warp-per-node softmax aggregation ----------------

template <int H, int F, bool LR, bool OUT_EXT>
__global__ __launch_bounds__(256) void k_agg(
    const float* __restrict__ bias, float* __restrict__ outext,
    int ostride, int n)
{
    constexpr int FOUT = H * F;
    constexpr int NJ = (FOUT + 31) / 32;

    int warp = (blockIdx.x * blockDim.x + threadIdx.x) >> 5;
    int lane = threadIdx.x & 31;
    if (warp >= n) return;
    int d = warp;

    float* out = OUT_EXT ? outext : g_x;

    int r0 = g_off[d], r1 = g_off[d + 1];
    if (r1 <= r0) return;   // can't happen (self loop), defensive

    float4 ad4 = *reinterpret_cast<const float4*>(&g_ald[d * 4]);
    float aldv[3] = {ad4.x, ad4.y, ad4.z};

    // pass 1: per-head max (lane-parallel)
    float m[H];
#pragma unroll
    for (int t = 0; t < H; t++) m[t] = -3.4e38f;
    for (int e = r0 + lane; e < r1; e += 32) {
        int s = __ldg(&g_csr[e]);
        float4 a4 = *reinterpret_cast<const float4*>(&g_als[s * 4]);
        float av[3] = {a4.x, a4.y, a4.z};
#pragma unroll
        for (int t = 0; t < H; t++) {
            float v = lrelu(av[t] + aldv[t]);
            m[t] = fmaxf(m[t], v);
        }
    }
#pragma unroll
    for (int o = 16; o > 0; o >>= 1)
#pragma unroll
        for (int t = 0; t < H; t++) m[t] = fmaxf(m[t], __shfl_xor_sync(0xffffffffu, m[t], o));

    // lane feature assignment
    int fidx[NJ]; int hidx[NJ]; bool fval[NJ];
#pragma unroll
    for (int j = 0; j < NJ; j++) {
        fidx[j] = lane + 32 * j;
        fval[j] = fidx[j] < FOUT;
        hidx[j] = fval[j] ? (fidx[j] / F) : 0;
    }

    // pass 2: 2 edges per iteration, branch-free, depth-2 prefetch
    float acc[NJ];
#pragma unroll
    for (int j = 0; j < NJ; j++) acc[j] = 0.f;
    float den[H];
#pragma unroll
    for (int t = 0; t < H; t++) den[t] = 0.f;

    int last = r1 - 1;
    int sA = __ldg(&g_csr[r0]);
    int sB = __ldg(&g_csr[(r0 + 1 < r1) ? r0 + 1 : last]);
    float4 aA = *reinterpret_cast<const float4*>(&g_als[sA * 4]);
    float4 aB = *reinterpret_cast<const float4*>(&g_als[sB * 4]);

    for (int e = r0; e < r1; e += 2) {
        // prefetch next pair
        int pC = (e + 2 <= last) ? e + 2 : last;
        int pD = (e + 3 <= last) ? e + 3 : last;
        int sC = __ldg(&g_csr[pC]);
        int sD = __ldg(&g_csr[pD]);
        float4 aC = *reinterpret_cast<const float4*>(&g_als[sC * 4]);
        float4 aD = *reinterpret_cast<const float4*>(&g_als[sD * 4]);

        bool vB = (e + 1 < r1);
        float avA[3] = {aA.x, aA.y, aA.z};
        float avB[3] = {aB.x, aB.y, aB.z};
        float wA[H], wB[H];
#pragma unroll
        for (int t = 0; t < H; t++) {
            float vAa = lrelu(avA[t] + aldv[t]);
            wA[t] = __expf(vAa - m[t]);
            float vBb = lrelu(avB[t] + aldv[t]);
            wB[t] = vB ? __expf(vBb - m[t]) : 0.f;
            den[t] += wA[t] + wB[t];
        }
        const float* hrA = g_h + (size_t)sA * HST;
        const float* hrB = g_h + (size_t)sB * HST;
#pragma unroll
        for (int j = 0; j < NJ; j++) {
            if (fval[j]) {
                float wa, wb;
                if (H == 1) { wa = wA[0]; wb = wB[0]; }
                else {
                    wa = (hidx[j] == 0) ? wA[0] : ((hidx[j] == 1) ? wA[1] : wA[2]);
                    wb = (hidx[j] == 0) ? wB[0] : ((hidx[j] == 1) ? wB[1] : wB[2]);
                }
                float a = fmaf(wa, __ldg(&hrA[fidx[j]]), acc[j]);
                acc[j] = fmaf(wb, __ldg(&hrB[fidx[j]]), a);
            }
        }
        sA = sC; aA = aC; sB = sD; aB = aD;
    }

    float inv[H];
#pragma unroll
    for (int t = 0; t < H; t++) inv[t] = 1.f / (den[t] + 1e-16f);

    float* orow = out + (size_t)d * ostride;
#pragma unroll
    for (int j = 0; j < NJ; j++) {
        if (fval[j]) {
            float ij;
            if (H == 1) ij = inv[0];
            else        ij = (hidx[j] == 0) ? inv[0] : ((hidx[j] == 1) ? inv[1] : inv[2]);
            float v = acc[j] * ij + __ldg(&bias[fidx[j]]);
            if (LR) v = lrelu(v);
            orow[fidx[j]] = v;
        }
    }
}

// ---------------- launch ----------------

extern "C" void kernel_launch(void* const* d_in, const int* in_sizes, int n_in,
                              void* d_out, int out_size)
{
    const float* x   = (const float*)d_in[0];
    const void*  ei  = d_in[1];
    const float* W0  = (const float*)d_in[2];
    const float* as0 = (const float*)d_in[3];
    const float* ad0 = (const float*)d_in[4];
    const float* b0  = (const float*)d_in[5];
    const float* W1  = (const float*)d_in[6];
    const float* as1 = (const float*)d_in[7];
    const float* ad1 = (const float*)d_in[8];
    const float* b1  = (const float*)d_in[9];
    const float* W2  = (const float*)d_in[10];
    const float* as2 = (const float*)d_in[11];
    const float* ad2 = (const float*)d_in[12];
    const float* b2  = (const float*)d_in[13];

    int n = in_sizes[0] / 6;       // 50000
    int E = in_sizes[1] / 2;       // 1600000
    if (n > NN) n = NN;
    if (E > EMAX) E = EMAX;

    int nblk = (n + 1023) / 1024;

    // CSR build
    k_init<<<(n + 255) / 256, 256>>>((const unsigned int*)ei, n);
    k_count<<<(E + 255) / 256, 256>>>(ei, E, n);
    k_scan1<<<nblk, 1024>>>(n);
    k_scan2<<<1, 1024>>>(nblk);
    k_total<<<1, 32>>>(n);
    k_scan3<<<nblk, 1024>>>(n);
    k_fill<<<(E + n + 255) / 256, 256>>>(ei, E, n);

    int gemm_blocks = (n + 63) / 64;
    int warp_blocks = (n + 7) / 8;

    // layer 0: in=6 -> 3x43 (concat 129), lrelu
    k_gemm<<<gemm_blocks, 256>>>(x, 1, 6, 6, W0, 129, n);
    k_al<3, 43><<<warp_blocks, 256>>>(as0, ad0, n);
    k_agg<3, 43, true, false><<<warp_blocks, 256>>>(b0, nullptr, HST, n);

    // layer 1: 129 -> 3x43 (concat 129), lrelu
    k_gemm<<<gemm_blocks, 256>>>(nullptr, 0, HST, 129, W1, 129, n);
    k_al<3, 43><<<warp_blocks, 256>>>(as1, ad1, n);
    k_agg<3, 43, true, false><<<warp_blocks, 256>>>(b1, nullptr, HST, n);

    // layer 2: 129 -> 1x128 (mean over 1 head), no final activation
    k_gemm<<<gemm_blocks, 256>>>(nullptr, 0, HST, 129, W2, 128, n);
    k_al<1, 128><<<warp_blocks, 256>>>(as2, ad2, n);
    k_agg<1, 128, false, true><<<warp_blocks, 256>>>(b2, (float*)d_out, 128, n);
}

// round 6
// speedup vs baseline: 1.1733x; 1.0506x over previous
#include <cuda_runtime.h>
#include <cuda_fp16.h>

// ----------------------------------------------------------------------------
// GAT encoder: 3 layers, N=50000 nodes, E=1.6M edges (+N self loops).
// R6 vs R5 (died): __align__(16) on all vector-accessed __device__ arrays.
//   __half array is only 2B-aligned by default; half2/float2/float4
//   reinterpret-casts need 4/8/16B. Misaligned wide LDG = device trap.
// R5 vs R4 (691us):
//   - h stored fp16 -> halves agg L2 bytes
//   - agg pass2 reads half2 feature pairs
//   - self-loop folded into scan1
// ----------------------------------------------------------------------------

#define NN    50000
#define EMAX  1600000
#define ETOT  (EMAX + NN)
#define HST   132          // padded row stride (elements) for h / x buffers
#define NEG   0.2f

__device__ int    g_is64;
__device__ int    g_cnt[NN];
__device__ int    g_off[NN + 1];
__device__ int    g_cur[NN];
__device__ int    g_part[64];
__device__ int    g_csr[ETOT];
__device__ __align__(16) __half g_hh[(size_t)NN * HST];  // fp16 hidden features
__device__ __align__(16) float  g_x[(size_t)NN * HST];   // fp32 layer input
__device__ __align__(16) float  g_als[NN * 4];           // stride 4: 3 heads = one LDG.128
__device__ __align__(16) float  g_ald[NN * 4];

__device__ __forceinline__ float lrelu(float v) { return v >= 0.f ? v : NEG * v; }

__device__ __forceinline__ int edge_at(const void* ei, size_t idx, int is64) {
    if (is64) return (int)((const long long*)ei)[idx];
    return ((const int*)ei)[idx];
}

// ---------------- init counts + dtype detection ----------------
__global__ void k_init(const unsigned int* __restrict__ w, int n) {
    int i = blockIdx.x * blockDim.x + threadIdx.x;
    if (i < n) g_cnt[i] = 0;
    if (i == 0) {
        int all0 = 1;
        for (int j = 1; j < 256; j += 2)
            if (w[j] != 0u) { all0 = 0; break; }
        g_is64 = all0;
    }
}

__global__ void k_count(const void* __restrict__ ei, int E, int n) {
    int i = blockIdx.x * blockDim.x + threadIdx.x;
    if (i >= E) return;
    int is64 = g_is64;
    int d = edge_at(ei, (size_t)E + i, is64);
    if ((unsigned)d < (unsigned)n) atomicAdd(&g_cnt[d], 1);
}

// ---------------- multi-block exclusive scan ----------------

__device__ __forceinline__ int blockScanExcl(int v, int tid, int* smem) {
    int lane = tid & 31, wid = tid >> 5;
    int x = v;
#pragma unroll
    for (int o = 1; o < 32; o <<= 1) {
        int t = __shfl_up_sync(0xffffffffu, x, o);
        if (lane >= o) x += t;
    }
    if (lane == 31) smem[wid] = x;
    __syncthreads();
    if (wid == 0) {
        int y = smem[lane];
#pragma unroll
        for (int o = 1; o < 32; o <<= 1) {
            int t = __shfl_up_sync(0xffffffffu, y, o);
            if (lane >= o) y += t;
        }
        smem[lane] = y;
    }
    __syncthreads();
    int base = (wid > 0) ? smem[wid - 1] : 0;
    return base + x - v;   // exclusive
}

__global__ __launch_bounds__(1024) void k_scan1(int n) {
    __shared__ int sw[32];
    int tid = threadIdx.x;
    int i = blockIdx.x * 1024 + tid;
    int v = (i < n) ? g_cnt[i] + 1 : 0;     // +1 = self loop
    int ex = blockScanExcl(v, tid, sw);
    if (i < n) g_off[i] = ex;
    if (tid == 1023) g_part[blockIdx.x] = ex + v;
}

__global__ __launch_bounds__(1024) void k_scan2(int nblk, int n) {
    __shared__ int sw[32];
    int tid = threadIdx.x;
    int v = (tid < nblk) ? g_part[tid] : 0;
    int ex = blockScanExcl(v, tid, sw);
    if (tid < nblk) g_part[tid] = ex;
    if (tid == nblk - 1) g_off[n] = ex + v;   // grand total
}

__global__ __launch_bounds__(1024) void k_scan3(int n) {
    int i = blockIdx.x * 1024 + threadIdx.x;
    if (i < n) {
        int o = g_off[i] + g_part[blockIdx.x];
        g_off[i] = o;
        g_cur[i] = o;
    }
}

__global__ void k_fill(const void* __restrict__ ei, int E, int n) {
    int i = blockIdx.x * blockDim.x + threadIdx.x;
    if (i >= E + n) return;
    int s, d;
    if (i < E) {
        int is64 = g_is64;
        s = edge_at(ei, (size_t)i, is64);
        d = edge_at(ei, (size_t)E + i, is64);
    } else {
        s = i - E; d = s;
    }
    if ((unsigned)s >= (unsigned)n || (unsigned)d >= (unsigned)n) return;
    int p = atomicAdd(&g_cur[d], 1);
    if ((unsigned)p < (unsigned)ETOT) g_csr[p] = s;
}

// ---------------- GEMM: h = x @ W  (fp32 math, fp16 store) ----------------

__global__ __launch_bounds__(256) void k_gemm(
    const float* __restrict__ xext, int use_ext, int xstride, int K,
    const float* __restrict__ W, int FOUT, int n)
{
    __shared__ float sx[64 * 129];
    const float* x = use_ext ? xext : g_x;
    int tid = threadIdx.x, warp = tid >> 5, lane = tid & 31;
    int nb = blockIdx.x * 64;

    int tot = 64 * K;
    for (int idx = tid; idx < tot; idx += 256) {
        int nl = idx / K, k = idx - nl * K;
        int gn = nb + nl;
        sx[idx] = (gn < n) ? x[(size_t)gn * xstride + k] : 0.f;
    }
    __syncthreads();

    float acc[8][5];
#pragma unroll
    for (int a = 0; a < 8; a++)
#pragma unroll
        for (int j = 0; j < 5; j++) acc[a][j] = 0.f;

    bool v4 = (lane + 128) < FOUT;        // FOUT is 128 or 129
    const float* sxw = sx + warp * 8 * K;

    for (int k = 0; k < K; k++) {
        const float* Wr = W + (size_t)k * FOUT + lane;
        float wv[5];
#pragma unroll
        for (int j = 0; j < 4; j++) wv[j] = __ldg(&Wr[32 * j]);
        wv[4] = v4 ? __ldg(&Wr[128]) : 0.f;
#pragma unroll
        for (int a = 0; a < 8; a++) {
            float xv = sxw[a * K + k];
#pragma unroll
            for (int j = 0; j < 5; j++) acc[a][j] = fmaf(xv, wv[j], acc[a][j]);
        }
    }

#pragma unroll
    for (int a = 0; a < 8; a++) {
        int gn = nb + warp * 8 + a;
        if (gn < n) {
            __half* hr = g_hh + (size_t)gn * HST;
#pragma unroll
            for (int j = 0; j < 4; j++) hr[lane + 32 * j] = __float2half(acc[a][j]);
            if (v4) hr[lane + 128] = __float2half(acc[a][4]);
        }
    }
}

// ---------------- attention scalars: warp per node ----------------

template <int H, int F>
__global__ __launch_bounds__(256) void k_al(
    const float* __restrict__ asr, const float* __restrict__ adt, int n)
{
    constexpr int FOUT = H * F;
    constexpr int NJ = (FOUT + 31) / 32;

    int warp = (blockIdx.x * blockDim.x + threadIdx.x) >> 5;
    int lane = threadIdx.x & 31;
    if (warp >= n) return;

    const __half* hr = g_hh + (size_t)warp * HST;

    float ps[H], pd[H];
#pragma unroll
    for (int t = 0; t < H; t++) { ps[t] = 0.f; pd[t] = 0.f; }

#pragma unroll
    for (int j = 0; j < NJ; j++) {
        int f = lane + 32 * j;
        if (f < FOUT) {
            float v = __half2float(hr[f]);
            float cs = v * __ldg(&asr[f]);
            float cd = v * __ldg(&adt[f]);
#pragma unroll
            for (int t = 0; t < H; t++) {
                bool in_t = (f >= t * F) && (f < (t + 1) * F);
                ps[t] += in_t ? cs : 0.f;
                pd[t] += in_t ? cd : 0.f;
            }
        }
    }
#pragma unroll
    for (int o = 16; o > 0; o >>= 1)
#pragma unroll
        for (int t = 0; t < H; t++) {
            ps[t] += __shfl_xor_sync(0xffffffffu, ps[t], o);
            pd[t] += __shfl_xor_sync(0xffffffffu, pd[t], o);
        }
    if (lane < H) {
        g_als[warp * 4 + lane] = (lane == 0) ? ps[0] : ((lane == 1 && H > 1) ? ps[1] : ps[H - 1]);
        g_ald[warp * 4 + lane] = (lane == 0) ? pd[0] : ((lane == 1 && H > 1) ? pd[1] : pd[H - 1]);
    }
}

// ---------------- warp-per-node softmax aggregation ----------------
// Pair layout: lane handles features {2*lane, 2*lane+1} in each 64-feature
// group -> half2 loads. FOUT=129 has one extra feature (128) handled by lane 0.

template <int H, int F, bool LR, bool OUT_EXT>
__global__ __launch_bounds__(256) void k_agg(
    const float* __restrict__ bias, float* __restrict__ outext,
    int ostride, int n)
{
    constexpr int FOUT  = H * F;
    constexpr int NP    = FOUT / 64;          // half2 pairs per lane (2)
    constexpr int EXTRA = FOUT - NP * 64;     // 0 or 1

    int warp = (blockIdx.x * blockDim.x + threadIdx.x) >> 5;
    int lane = threadIdx.x & 31;
    if (warp >= n) return;
    int d = warp;

    float* out = OUT_EXT ? outext : g_x;

    int r0 = g_off[d], r1 = g_off[d + 1];
    if (r1 <= r0) return;

    float4 ad4 = *reinterpret_cast<const float4*>(&g_ald[d * 4]);
    float aldv[3] = {ad4.x, ad4.y, ad4.z};

    // pass 1: per-head max (lane-parallel)
    float m[H];
#pragma unroll
    for (int t = 0; t < H; t++) m[t] = -3.4e38f;
    for (int e = r0 + lane; e < r1; e += 32) {
        int s = __ldg(&g_csr[e]);
        float4 a4 = *reinterpret_cast<const float4*>(&g_als[s * 4]);
        float av[3] = {a4.x, a4.y, a4.z};
#pragma unroll
        for (int t = 0; t < H; t++) {
            float v = lrelu(av[t] + aldv[t]);
            m[t] = fmaxf(m[t], v);
        }
    }
#pragma unroll
    for (int o = 16; o > 0; o >>= 1)
#pragma unroll
        for (int t = 0; t < H; t++) m[t] = fmaxf(m[t], __shfl_xor_sync(0xffffffffu, m[t], o));

    // per-lane feature pair -> head mapping
    int hp0[NP], hp1[NP];
#pragma unroll
    for (int j = 0; j < NP; j++) {
        int f0 = 2 * lane + 64 * j;
        hp0[j] = f0 / F;
        hp1[j] = (f0 + 1) / F;
    }

    // pass 2: 2 edges / iteration, half2 gathers
    float acc0[NP], acc1[NP], accX = 0.f;
#pragma unroll
    for (int j = 0; j < NP; j++) { acc0[j] = 0.f; acc1[j] = 0.f; }
    float den[H];
#pragma unroll
    for (int t = 0; t < H; t++) den[t] = 0.f;

    int last = r1 - 1;
    int sA = __ldg(&g_csr[r0]);
    int sB = __ldg(&g_csr[(r0 + 1 < r1) ? r0 + 1 : last]);
    float4 aA = *reinterpret_cast<const float4*>(&g_als[sA * 4]);
    float4 aB = *reinterpret_cast<const float4*>(&g_als[sB * 4]);

    for (int e = r0; e < r1; e += 2) {
        int pC = (e + 2 <= last) ? e + 2 : last;
        int pD = (e + 3 <= last) ? e + 3 : last;
        int sC = __ldg(&g_csr[pC]);
        int sD = __ldg(&g_csr[pD]);
        float4 aC = *reinterpret_cast<const float4*>(&g_als[sC * 4]);
        float4 aD = *reinterpret_cast<const float4*>(&g_als[sD * 4]);

        bool vB = (e + 1 < r1);
        float avA[3] = {aA.x, aA.y, aA.z};
        float avB[3] = {aB.x, aB.y, aB.z};
        float wA[H], wB[H];
#pragma unroll
        for (int t = 0; t < H; t++) {
            wA[t] = __expf(lrelu(avA[t] + aldv[t]) - m[t]);
            float wb = __expf(lrelu(avB[t] + aldv[t]) - m[t]);
            wB[t] = vB ? wb : 0.f;
            den[t] += wA[t] + wB[t];
        }

        const __half2* hA = reinterpret_cast<const __half2*>(g_hh + (size_t)sA * HST);
        const __half2* hB = reinterpret_cast<const __half2*>(g_hh + (size_t)sB * HST);
#pragma unroll
        for (int j = 0; j < NP; j++) {
            float wa0, wa1, wb0, wb1;
            if (H == 1) { wa0 = wA[0]; wa1 = wA[0]; wb0 = wB[0]; wb1 = wB[0]; }
            else {
                wa0 = (hp0[j] == 0) ? wA[0] : ((hp0[j] == 1) ? wA[1] : wA[2]);
                wa1 = (hp1[j] == 0) ? wA[0] : ((hp1[j] == 1) ? wA[1] : wA[2]);
                wb0 = (hp0[j] == 0) ? wB[0] : ((hp0[j] == 1) ? wB[1] : wB[2]);
                wb1 = (hp1[j] == 0) ? wB[0] : ((hp1[j] == 1) ? wB[1] : wB[2]);
            }
            float2 fa = __half22float2(__ldg(&hA[lane + 32 * j]));
            float2 fb = __half22float2(__ldg(&hB[lane + 32 * j]));
            acc0[j] = fmaf(wa0, fa.x, acc0[j]);
            acc1[j] = fmaf(wa1, fa.y, acc1[j]);
            acc0[j] = fmaf(wb0, fb.x, acc0[j]);
            acc1[j] = fmaf(wb1, fb.y, acc1[j]);
        }
        if (EXTRA && lane == 0) {
            float ha = __half2float(__ldg(&g_hh[(size_t)sA * HST + NP * 64]));
            float hb = __half2float(__ldg(&g_hh[(size_t)sB * HST + NP * 64]));
            accX = fmaf(wA[H - 1], ha, accX);
            accX = fmaf(wB[H - 1], hb, accX);
        }
        sA = sC; aA = aC; sB = sD; aB = aD;
    }

    float inv[H];
#pragma unroll
    for (int t = 0; t < H; t++) inv[t] = 1.f / (den[t] + 1e-16f);

    float* orow = out + (size_t)d * ostride;
#pragma unroll
    for (int j = 0; j < NP; j++) {
        int f0 = 2 * lane + 64 * j;
        float i0, i1;
        if (H == 1) { i0 = inv[0]; i1 = inv[0]; }
        else {
            i0 = (hp0[j] == 0) ? inv[0] : ((hp0[j] == 1) ? inv[1] : inv[2]);
            i1 = (hp1[j] == 0) ? inv[0] : ((hp1[j] == 1) ? inv[1] : inv[2]);
        }
        float2 o;
        o.x = acc0[j] * i0 + __ldg(&bias[f0]);
        o.y = acc1[j] * i1 + __ldg(&bias[f0 + 1]);
        if (LR) { o.x = lrelu(o.x); o.y = lrelu(o.y); }
        *reinterpret_cast<float2*>(&orow[f0]) = o;
    }
    if (EXTRA && lane == 0) {
        float v = accX * inv[H - 1] + __ldg(&bias[NP * 64]);
        if (LR) v = lrelu(v);
        orow[NP * 64] = v;
    }
}

// ---------------- launch ----------------

extern "C" void kernel_launch(void* const* d_in, const int* in_sizes, int n_in,
                              void* d_out, int out_size)
{
    const float* x   = (const float*)d_in[0];
    const void*  ei  = d_in[1];
    const float* W0  = (const float*)d_in[2];
    const float* as0 = (const float*)d_in[3];
    const float* ad0 = (const float*)d_in[4];
    const float* b0  = (const float*)d_in[5];
    const float* W1  = (const float*)d_in[6];
    const float* as1 = (const float*)d_in[7];
    const float* ad1 = (const float*)d_in[8];
    const float* b1  = (const float*)d_in[9];
    const float* W2  = (const float*)d_in[10];
    const float* as2 = (const float*)d_in[11];
    const float* ad2 = (const float*)d_in[12];
    const float* b2  = (const float*)d_in[13];

    int n = in_sizes[0] / 6;       // 50000
    int E = in_sizes[1] / 2;       // 1600000
    if (n > NN) n = NN;
    if (E > EMAX) E = EMAX;

    int nblk = (n + 1023) / 1024;

    // CSR build
    k_init<<<(n + 255) / 256, 256>>>((const unsigned int*)ei, n);
    k_count<<<(E + 255) / 256, 256>>>(ei, E, n);
    k_scan1<<<nblk, 1024>>>(n);
    k_scan2<<<1, 1024>>>(nblk, n);
    k_scan3<<<nblk, 1024>>>(n);
    k_fill<<<(E + n + 255) / 256, 256>>>(ei, E, n);

    int gemm_blocks = (n + 63) / 64;
    int warp_blocks = (n + 7) / 8;

    // layer 0: in=6 -> 3x43 (concat 129), lrelu
    k_gemm<<<gemm_blocks, 256>>>(x, 1, 6, 6, W0, 129, n);
    k_al<3, 43><<<warp_blocks, 256>>>(as0, ad0, n);
    k_agg<3, 43, true, false><<<warp_blocks, 256>>>(b0, nullptr, HST, n);

    // layer 1: 129 -> 3x43 (concat 129), lrelu
    k_gemm<<<gemm_blocks, 256>>>(nullptr, 0, HST, 129, W1, 129, n);
    k_al<3, 43><<<warp_blocks, 256>>>(as1, ad1, n);
    k_agg<3, 43, true, false><<<warp_blocks, 256>>>(b1, nullptr, HST, n);

    // layer 2: 129 -> 1x128 (mean over 1 head), no final activation
    k_gemm<<<gemm_blocks, 256>>>(nullptr, 0, HST, 129, W2, 128, n);
    k_al<1, 128><<<warp_blocks, 256>>>(as2, ad2, n);
    k_agg<1, 128, false, true><<<warp_blocks, 256>>>(b2, (float*)d_out, 128, n);
}